// round 10
// baseline (speedup 1.0000x reference)
#include <cuda_runtime.h>
#include <cuda_bf16.h>
#include <math.h>

#define B_   8
#define CIN  128
#define CK   64
#define CV   64
#define CO   128
#define N_   4096
#define KVCHUNKS 32

// ---------------- scratch ----------------
__device__ float g_yq[B_ * CK * N_];
__device__ float g_yk[B_ * CK * N_];
__device__ float g_yv[B_ * CV * N_];
__device__ float g_scale[2 * CK];
__device__ float g_shift[2 * CK];
__device__ float g_spart[2 * 64 * 512];   // [which*64+c][b*64+nblk]
__device__ float g_sspart[2 * 64 * 512];
__device__ float g_vpart[512 * 64];       // [b*64+cv][nblk]
__device__ float g_vsum[B_ * CV];
__device__ float g_kvpart[KVCHUNKS * B_ * CK * CV];
__device__ float g_M[B_ * CO * CK];       // transposed [b][co][ck]
__device__ float g_obias[B_ * CO];

// ---------------- mma / ldmatrix helpers ----------------
__device__ __forceinline__ unsigned su32(const void* p) {
    return (unsigned)__cvta_generic_to_shared(p);
}
#define LDSM_X4(r, addr) \
    asm volatile("ldmatrix.sync.aligned.m8n8.x4.shared.b16 {%0,%1,%2,%3}, [%4];" \
        : "=r"((r)[0]), "=r"((r)[1]), "=r"((r)[2]), "=r"((r)[3]) : "r"(addr))
#define LDSM_X4T(r, addr) \
    asm volatile("ldmatrix.sync.aligned.m8n8.x4.trans.shared.b16 {%0,%1,%2,%3}, [%4];" \
        : "=r"((r)[0]), "=r"((r)[1]), "=r"((r)[2]), "=r"((r)[3]) : "r"(addr))
#define MMA_BF16(d, a, b0, b1) \
    asm volatile("mma.sync.aligned.m16n8k16.row.col.f32.bf16.bf16.f32 " \
        "{%0,%1,%2,%3}, {%4,%5,%6,%7}, {%8,%9}, {%0,%1,%2,%3};" \
        : "+f"((d)[0]), "+f"((d)[1]), "+f"((d)[2]), "+f"((d)[3]) \
        : "r"((a)[0]), "r"((a)[1]), "r"((a)[2]), "r"((a)[3]), "r"(b0), "r"(b1))

__device__ __forceinline__ unsigned packbf(__nv_bfloat16 lo, __nv_bfloat16 hi) {
    return ((unsigned)__bfloat16_as_ushort(hi) << 16) | __bfloat16_as_ushort(lo);
}
__device__ __forceinline__ void split4(float4 f, uint2 &hi, uint2 &lo) {
    __nv_bfloat16 hx = __float2bfloat16(f.x), hy = __float2bfloat16(f.y);
    __nv_bfloat16 hz = __float2bfloat16(f.z), hw = __float2bfloat16(f.w);
    __nv_bfloat16 lx = __float2bfloat16(f.x - __bfloat162float(hx));
    __nv_bfloat16 ly = __float2bfloat16(f.y - __bfloat162float(hy));
    __nv_bfloat16 lz = __float2bfloat16(f.z - __bfloat162float(hz));
    __nv_bfloat16 lw = __float2bfloat16(f.w - __bfloat162float(hw));
    hi.x = packbf(hx, hy); hi.y = packbf(hz, hw);
    lo.x = packbf(lx, ly); lo.y = packbf(lz, lw);
}

#define ASTR 72
#define BSTR 72

// ---------------- K1: conv via bf16-split MMA + fused stats partials --------
// grid (64, B_, 3), 256 threads.
__global__ __launch_bounds__(256) void conv_mma_kernel(
    const float* __restrict__ xq, const float* __restrict__ xk,
    const float* __restrict__ xv,
    const float* __restrict__ Wk, const float* __restrict__ Wv,
    const float* __restrict__ bk, const float* __restrict__ bv)
{
    int which = blockIdx.z;
    const float* x    = (which == 0) ? xq : (which == 1) ? xk : xv;
    const float* W    = (which == 2) ? Wv : Wk;
    const float* bias = (which == 2) ? bv : bk;
    float* y          = (which == 0) ? g_yq : (which == 1) ? g_yk : g_yv;

    int bb = blockIdx.y;
    int n0 = blockIdx.x * 64;
    int tid = threadIdx.x;
    int lane = tid & 31, w = tid >> 5;
    int ct = (w & 3) * 16;
    int ng = (w >> 2) * 32;

    __shared__ __align__(16) __nv_bfloat16 Ah[64 * ASTR];
    __shared__ __align__(16) __nv_bfloat16 Al[64 * ASTR];
    __shared__ __align__(16) __nv_bfloat16 Bh[64 * BSTR];
    __shared__ __align__(16) __nv_bfloat16 Bl[64 * BSTR];

    int q = lane >> 3, rr = lane & 7;
    unsigned aOffH, aOffL, bOffH0, bOffL0, bOffH1, bOffL1;
    {
        int arow = ct + (q & 1) * 8 + rr;
        int acol = (q >> 1) * 8;
        aOffH = su32(Ah) + arow * (ASTR * 2) + acol * 2;
        aOffL = su32(Al) + arow * (ASTR * 2) + acol * 2;
        int brow = (q & 1) * 8 + rr;
        int bcol0 = ng + (q >> 1) * 8;
        int bcol1 = ng + 16 + (q >> 1) * 8;
        bOffH0 = su32(Bh) + brow * (BSTR * 2) + bcol0 * 2;
        bOffL0 = su32(Bl) + brow * (BSTR * 2) + bcol0 * 2;
        bOffH1 = su32(Bh) + brow * (BSTR * 2) + bcol1 * 2;
        bOffL1 = su32(Bl) + brow * (BSTR * 2) + bcol1 * 2;
    }

    float acc[4][4] = {};

    for (int s = 0; s < 2; s++) {
        #pragma unroll
        for (int i = 0; i < 4; i++) {
            int e = tid + i * 256;
            int co = e >> 4, ci4 = (e & 15) * 4;
            float4 f = *(const float4*)&W[co * CIN + s * 64 + ci4];
            uint2 hi, lo; split4(f, hi, lo);
            *(uint2*)&Ah[co * ASTR + ci4] = hi;
            *(uint2*)&Al[co * ASTR + ci4] = lo;
        }
        #pragma unroll
        for (int i = 0; i < 4; i++) {
            int e = tid + i * 256;
            int ci = e >> 4, nn4 = (e & 15) * 4;
            float4 f = *(const float4*)&x[((size_t)(bb * CIN + s * 64 + ci)) * N_ + n0 + nn4];
            uint2 hi, lo; split4(f, hi, lo);
            *(uint2*)&Bh[ci * BSTR + nn4] = hi;
            *(uint2*)&Bl[ci * BSTR + nn4] = lo;
        }
        __syncthreads();

        #pragma unroll
        for (int ks = 0; ks < 4; ks++) {
            unsigned aStep = ks * 32;
            unsigned bStep = ks * 16 * (BSTR * 2);
            unsigned ah[4], al[4], bh[4], bl[4], bh2[4], bl2[4];
            LDSM_X4(ah, aOffH + aStep);
            LDSM_X4(al, aOffL + aStep);
            LDSM_X4T(bh, bOffH0 + bStep);
            LDSM_X4T(bl, bOffL0 + bStep);
            LDSM_X4T(bh2, bOffH1 + bStep);
            LDSM_X4T(bl2, bOffL1 + bStep);
            MMA_BF16(acc[0], ah, bh[0], bh[1]);
            MMA_BF16(acc[0], ah, bl[0], bl[1]);
            MMA_BF16(acc[0], al, bh[0], bh[1]);
            MMA_BF16(acc[1], ah, bh[2], bh[3]);
            MMA_BF16(acc[1], ah, bl[2], bl[3]);
            MMA_BF16(acc[1], al, bh[2], bh[3]);
            MMA_BF16(acc[2], ah, bh2[0], bh2[1]);
            MMA_BF16(acc[2], ah, bl2[0], bl2[1]);
            MMA_BF16(acc[2], al, bh2[0], bh2[1]);
            MMA_BF16(acc[3], ah, bh2[2], bh2[3]);
            MMA_BF16(acc[3], ah, bl2[2], bl2[3]);
            MMA_BF16(acc[3], al, bh2[2], bh2[3]);
        }
        __syncthreads();
    }

    // epilogue: bias+store, fused per-block stats partials
    int r4 = lane >> 2, c2 = (lane & 3) * 2;
    int row0 = ct + r4, row1 = ct + r4 + 8;
    float b0v = bias[row0], b1v = bias[row1];
    float s0 = 0.f, ss0 = 0.f, s1 = 0.f, ss1 = 0.f;
    #pragma unroll
    for (int t = 0; t < 4; t++) {
        int col = n0 + ng + t * 8 + c2;
        float v00 = acc[t][0] + b0v, v01 = acc[t][1] + b0v;
        float v10 = acc[t][2] + b1v, v11 = acc[t][3] + b1v;
        *(float2*)&y[((size_t)(bb * 64 + row0)) * N_ + col] = make_float2(v00, v01);
        *(float2*)&y[((size_t)(bb * 64 + row1)) * N_ + col] = make_float2(v10, v11);
        s0 += v00 + v01;  ss0 += v00 * v00 + v01 * v01;
        s1 += v10 + v11;  ss1 += v10 * v10 + v11 * v11;
    }
    float* red_s  = (float*)Ah;   // smem reuse post-sync: 64 rows x 8 slots
    float* red_ss = (float*)Bh;
    int slot = ((w >> 2) << 2) | (lane & 3);
    red_s[row0 * 8 + slot] = s0;  red_ss[row0 * 8 + slot] = ss0;
    red_s[row1 * 8 + slot] = s1;  red_ss[row1 * 8 + slot] = ss1;
    __syncthreads();
    if (tid < 64) {
        float S = 0.f, SS = 0.f;
        #pragma unroll
        for (int i = 0; i < 8; i++) { S += red_s[tid * 8 + i]; SS += red_ss[tid * 8 + i]; }
        if (which == 2) {
            g_vpart[(bb * 64 + tid) * 64 + blockIdx.x] = S;
        } else {
            int o = which * 64 + tid;
            g_spart[o * 512 + bb * 64 + blockIdx.x]  = S;
            g_sspart[o * 512 + bb * 64 + blockIdx.x] = SS;
        }
    }
}

// ---------------- K2: reduce partials -> BN scale/shift, vsum ----------------
__global__ __launch_bounds__(128) void stats_reduce_kernel(
    const float* __restrict__ gamma, const float* __restrict__ beta)
{
    int gid = blockIdx.x * 128 + threadIdx.x;
    if (gid < 128) {
        int c = gid & 63;
        float S = 0.f, SS = 0.f;
        #pragma unroll 8
        for (int i = 0; i < 512; i++) {
            S  += g_spart[gid * 512 + i];
            SS += g_sspart[gid * 512 + i];
        }
        const float inv = 1.0f / 32768.0f;
        float mean = S * inv;
        float var  = SS * inv - mean * mean;
        float sc = gamma[c] * rsqrtf(var + 1e-5f);
        g_scale[gid] = sc;
        g_shift[gid] = beta[c] - mean * sc;
    } else if (gid < 640) {
        int t = gid - 128;
        float S = 0.f;
        #pragma unroll
        for (int i = 0; i < 64; i++) S += g_vpart[t * 64 + i];
        g_vsum[t] = S;
    }
}

// ---------------- K3: apply BN + L2-normalize (512 thr, float2, 2 cols) ------
// grid 256; block covers 256 columns; thread: 16 channels x 2 columns.
__global__ __launch_bounds__(512) void norm_kernel() {
    int blk = blockIdx.x;
    int which = blk >> 7;
    int r = blk & 127;
    int b = r >> 4;
    int n0 = (r & 15) * 256;
    float* y = which ? g_yk : g_yq;
    int tid = threadIdx.x;
    int qt = tid >> 7;           // channel quarter 0..3
    int l = tid & 127;
    int n = n0 + l * 2;

    __shared__ float scs[64], shs[64];
    __shared__ float ss4[4][256];
    if (tid < 64) {
        scs[tid] = g_scale[which * 64 + tid];
        shs[tid] = g_shift[which * 64 + tid];
    }
    __syncthreads();

    float2 v[16];
    float ssa = 0.f, ssb = 0.f;
    #pragma unroll
    for (int i = 0; i < 16; i++) {
        int c = qt * 16 + i;
        float2 t = *(const float2*)&y[((size_t)(b * 64 + c)) * N_ + n];
        t.x = t.x * scs[c] + shs[c];
        t.y = t.y * scs[c] + shs[c];
        v[i] = t;
        ssa += t.x * t.x;  ssb += t.y * t.y;
    }
    ss4[qt][l * 2] = ssa;  ss4[qt][l * 2 + 1] = ssb;
    __syncthreads();
    float rna = 1.0f / (sqrtf(ss4[0][l*2]   + ss4[1][l*2]   + ss4[2][l*2]   + ss4[3][l*2])   + 1e-7f);
    float rnb = 1.0f / (sqrtf(ss4[0][l*2+1] + ss4[1][l*2+1] + ss4[2][l*2+1] + ss4[3][l*2+1]) + 1e-7f);
    #pragma unroll
    for (int i = 0; i < 16; i++) {
        int c = qt * 16 + i;
        *(float2*)&y[((size_t)(b * 64 + c)) * N_ + n] = make_float2(v[i].x * rna, v[i].y * rnb);
    }
}

// ---------------- K4: KV via bf16-split MMA (vsum removed) -------------------
__global__ __launch_bounds__(256) void kv_mma_kernel() {
    int chunk = blockIdx.x, b = blockIdx.y;
    int tid = threadIdx.x;
    int lane = tid & 31, w = tid >> 5;
    int ct = (w & 3) * 16;
    int cg = (w >> 2) * 32;

    __shared__ __align__(16) __nv_bfloat16 Kh[64 * ASTR];
    __shared__ __align__(16) __nv_bfloat16 Kl[64 * ASTR];
    __shared__ __align__(16) __nv_bfloat16 Vh[64 * ASTR];
    __shared__ __align__(16) __nv_bfloat16 Vl[64 * ASTR];

    int q = lane >> 3, rr = lane & 7;
    unsigned aH, aL, bH0, bL0, bH1, bL1;
    {
        int arow = ct + (q & 1) * 8 + rr;
        int acol = (q >> 1) * 8;
        aH = su32(Kh) + arow * (ASTR * 2) + acol * 2;
        aL = su32(Kl) + arow * (ASTR * 2) + acol * 2;
        int brow = cg + (q >> 1) * 8 + rr;
        int bcol = (q & 1) * 8;
        bH0 = su32(Vh) + brow * (ASTR * 2) + bcol * 2;
        bL0 = su32(Vl) + brow * (ASTR * 2) + bcol * 2;
        bH1 = bH0 + 16 * (ASTR * 2);
        bL1 = bL0 + 16 * (ASTR * 2);
    }

    float acc[4][4] = {};

    for (int t = 0; t < 2; t++) {
        int n0 = chunk * 128 + t * 64;
        #pragma unroll
        for (int i = 0; i < 4; i++) {
            int e = tid + i * 256;
            int row = e >> 4, nn4 = (e & 15) * 4;
            float4 fk = *(const float4*)&g_yk[((size_t)(b * 64 + row)) * N_ + n0 + nn4];
            float4 fv = *(const float4*)&g_yv[((size_t)(b * 64 + row)) * N_ + n0 + nn4];
            uint2 hi, lo;
            split4(fk, hi, lo);
            *(uint2*)&Kh[row * ASTR + nn4] = hi;
            *(uint2*)&Kl[row * ASTR + nn4] = lo;
            split4(fv, hi, lo);
            *(uint2*)&Vh[row * ASTR + nn4] = hi;
            *(uint2*)&Vl[row * ASTR + nn4] = lo;
        }
        __syncthreads();

        #pragma unroll
        for (int ks = 0; ks < 4; ks++) {
            unsigned step = ks * 32;
            unsigned ah[4], al[4], bh[4], bl[4], bh2[4], bl2[4];
            LDSM_X4(ah, aH + step);
            LDSM_X4(al, aL + step);
            LDSM_X4(bh, bH0 + step);
            LDSM_X4(bl, bL0 + step);
            LDSM_X4(bh2, bH1 + step);
            LDSM_X4(bl2, bL1 + step);
            MMA_BF16(acc[0], ah, bh[0], bh[1]);
            MMA_BF16(acc[0], ah, bl[0], bl[1]);
            MMA_BF16(acc[0], al, bh[0], bh[1]);
            MMA_BF16(acc[1], ah, bh[2], bh[3]);
            MMA_BF16(acc[1], ah, bl[2], bl[3]);
            MMA_BF16(acc[1], al, bh[2], bh[3]);
            MMA_BF16(acc[2], ah, bh2[0], bh2[1]);
            MMA_BF16(acc[2], ah, bl2[0], bl2[1]);
            MMA_BF16(acc[2], al, bh2[0], bh2[1]);
            MMA_BF16(acc[3], ah, bh2[2], bh2[3]);
            MMA_BF16(acc[3], ah, bl2[2], bl2[3]);
            MMA_BF16(acc[3], al, bh2[2], bh2[3]);
        }
        __syncthreads();
    }

    int r4 = lane >> 2, c2 = (lane & 3) * 2;
    int row0 = ct + r4, row1 = ct + r4 + 8;
    float* base = &g_kvpart[(((size_t)chunk * B_ + b)) * 4096];
    #pragma unroll
    for (int t = 0; t < 4; t++) {
        int col = cg + t * 8 + c2;
        *(float2*)&base[row0 * 64 + col] = make_float2(acc[t][0], acc[t][1]);
        *(float2*)&base[row1 * 64 + col] = make_float2(acc[t][2], acc[t][3]);
    }
}

// ---------------- K5: M^T = (KV @ Ww^T)^T; obias ----------------------------
__global__ __launch_bounds__(256) void m_kernel(
    const float* __restrict__ Ww, const float* __restrict__ bw)
{
    int b = blockIdx.x;
    __shared__ float KVs[64][64];
    __shared__ float WwT[64][128];
    __shared__ float vs_s[64];
    int tid = threadIdx.x;

    if (tid < 64) vs_s[tid] = g_vsum[b * 64 + tid];
    for (int e = tid; e < 4096; e += 256) {
        float s = 0.f;
        #pragma unroll
        for (int c2 = 0; c2 < KVCHUNKS; c2++)
            s += g_kvpart[((size_t)c2 * B_ + b) * 4096 + e];
        KVs[e >> 6][e & 63] = s;
    }
    for (int e = tid; e < 8192; e += 256) {
        int cv = e >> 7, co = e & 127;
        WwT[cv][co] = Ww[co * CV + cv];
    }
    __syncthreads();

    int co = tid & 127;
    for (int ck = (tid >> 7); ck < 64; ck += 2) {
        float s = 0.f;
        #pragma unroll 8
        for (int cv = 0; cv < 64; cv++) s += KVs[ck][cv] * WwT[cv][co];
        g_M[((size_t)b * 128 + co) * 64 + ck] = s;
    }
    if (tid < 128) {
        float s = bw[tid];
        #pragma unroll 8
        for (int cv = 0; cv < 64; cv++) s += vs_s[cv] * WwT[cv][tid];
        g_obias[b * CO + tid] = s;
    }
}

// ---------------- K6: out via bf16-split MMA (R9, unchanged) -----------------
__global__ __launch_bounds__(256) void out_mma_kernel(float* __restrict__ out) {
    int b = blockIdx.y, n0 = blockIdx.x * 64, ch = blockIdx.z;
    int co0 = ch * 64;
    int tid = threadIdx.x;
    int lane = tid & 31, w = tid >> 5;
    int ct = (w & 3) * 16;
    int ng = (w >> 2) * 32;

    __shared__ __align__(16) __nv_bfloat16 Ah[64 * ASTR];
    __shared__ __align__(16) __nv_bfloat16 Al[64 * ASTR];
    __shared__ __align__(16) __nv_bfloat16 Bh[64 * BSTR];
    __shared__ __align__(16) __nv_bfloat16 Bl[64 * BSTR];

    int q = lane >> 3, rr = lane & 7;
    unsigned aOffH, aOffL, bOffH0, bOffL0, bOffH1, bOffL1;
    {
        int arow = ct + (q & 1) * 8 + rr;
        int acol = (q >> 1) * 8;
        aOffH = su32(Ah) + arow * (ASTR * 2) + acol * 2;
        aOffL = su32(Al) + arow * (ASTR * 2) + acol * 2;
        int brow = (q & 1) * 8 + rr;
        int bcol0 = ng + (q >> 1) * 8;
        int bcol1 = ng + 16 + (q >> 1) * 8;
        bOffH0 = su32(Bh) + brow * (BSTR * 2) + bcol0 * 2;
        bOffL0 = su32(Bl) + brow * (BSTR * 2) + bcol0 * 2;
        bOffH1 = su32(Bh) + brow * (BSTR * 2) + bcol1 * 2;
        bOffL1 = su32(Bl) + brow * (BSTR * 2) + bcol1 * 2;
    }

    #pragma unroll
    for (int i = 0; i < 4; i++) {
        int e = tid + i * 256;
        int row = e >> 4, ck4 = (e & 15) * 4;
        float4 f = *(const float4*)&g_M[((size_t)b * 128 + co0 + row) * 64 + ck4];
        uint2 hi, lo; split4(f, hi, lo);
        *(uint2*)&Ah[row * ASTR + ck4] = hi;
        *(uint2*)&Al[row * ASTR + ck4] = lo;
    }
    #pragma unroll
    for (int i = 0; i < 4; i++) {
        int e = tid + i * 256;
        int ck = e >> 4, nn4 = (e & 15) * 4;
        float4 f = *(const float4*)&g_yq[((size_t)(b * 64 + ck)) * N_ + n0 + nn4];
        uint2 hi, lo; split4(f, hi, lo);
        *(uint2*)&Bh[ck * BSTR + nn4] = hi;
        *(uint2*)&Bl[ck * BSTR + nn4] = lo;
    }
    __syncthreads();

    float acc[4][4] = {};
    #pragma unroll
    for (int ks = 0; ks < 4; ks++) {
        unsigned aStep = ks * 32;
        unsigned bStep = ks * 16 * (BSTR * 2);
        unsigned ah[4], al[4], bh[4], bl[4], bh2[4], bl2[4];
        LDSM_X4(ah, aOffH + aStep);
        LDSM_X4(al, aOffL + aStep);
        LDSM_X4T(bh, bOffH0 + bStep);
        LDSM_X4T(bl, bOffL0 + bStep);
        LDSM_X4T(bh2, bOffH1 + bStep);
        LDSM_X4T(bl2, bOffL1 + bStep);
        MMA_BF16(acc[0], ah, bh[0], bh[1]);
        MMA_BF16(acc[0], ah, bl[0], bl[1]);
        MMA_BF16(acc[0], al, bh[0], bh[1]);
        MMA_BF16(acc[1], ah, bh[2], bh[3]);
        MMA_BF16(acc[1], ah, bl[2], bl[3]);
        MMA_BF16(acc[1], al, bh[2], bh[3]);
        MMA_BF16(acc[2], ah, bh2[0], bh2[1]);
        MMA_BF16(acc[2], ah, bl2[0], bl2[1]);
        MMA_BF16(acc[2], al, bh2[0], bh2[1]);
        MMA_BF16(acc[3], ah, bh2[2], bh2[3]);
        MMA_BF16(acc[3], ah, bl2[2], bl2[3]);
        MMA_BF16(acc[3], al, bh2[2], bh2[3]);
    }

    int r4 = lane >> 2, c2 = (lane & 3) * 2;
    int row0 = co0 + ct + r4, row1 = row0 + 8;
    float b0v = g_obias[b * CO + row0], b1v = g_obias[b * CO + row1];
    #pragma unroll
    for (int t = 0; t < 4; t++) {
        int col = n0 + ng + t * 8 + c2;
        *(float2*)&out[((size_t)(b * CO + row0)) * N_ + col] =
            make_float2(acc[t][0] + b0v, acc[t][1] + b0v);
        *(float2*)&out[((size_t)(b * CO + row1)) * N_ + col] =
            make_float2(acc[t][2] + b1v, acc[t][3] + b1v);
    }
}

// ---------------- launch ----------------
extern "C" void kernel_launch(void* const* d_in, const int* in_sizes, int n_in,
                              void* d_out, int out_size) {
    const float* q     = (const float*)d_in[0];
    const float* k     = (const float*)d_in[1];
    const float* v     = (const float*)d_in[2];
    const float* Wk    = (const float*)d_in[3];
    const float* bk    = (const float*)d_in[4];
    const float* gamma = (const float*)d_in[5];
    const float* beta  = (const float*)d_in[6];
    const float* Wv    = (const float*)d_in[7];
    const float* bv    = (const float*)d_in[8];
    const float* Ww    = (const float*)d_in[9];
    const float* bw    = (const float*)d_in[10];
    float* out = (float*)d_out;

    conv_mma_kernel<<<dim3(64, B_, 3), 256>>>(q, k, v, Wk, Wv, bk, bv);
    stats_reduce_kernel<<<5, 128>>>(gamma, beta);
    norm_kernel<<<256, 512>>>();
    kv_mma_kernel<<<dim3(KVCHUNKS, B_), 256>>>();
    m_kernel<<<B_, 256>>>(Ww, bw);
    out_mma_kernel<<<dim3(64, B_, 2), 256>>>(out);
}

// round 11
// speedup vs baseline: 1.4294x; 1.4294x over previous
#include <cuda_runtime.h>
#include <cuda_bf16.h>
#include <math.h>

#define B_   8
#define CIN  128
#define CK   64
#define CV   64
#define CO   128
#define N_   4096
#define KVCHUNKS 64

// ---------------- scratch ----------------
__device__ float g_yq[B_ * CK * N_];
__device__ float g_yk[B_ * CK * N_];
__device__ float g_yv[B_ * CV * N_];
__device__ float g_scale[2 * CK];
__device__ float g_shift[2 * CK];
__device__ float g_vsumpart[KVCHUNKS * B_ * CV];
__device__ float g_kvpart[KVCHUNKS * B_ * CK * CV];
__device__ float g_M[B_ * CO * CK];      // TRANSPOSED: [b][co][ck]
__device__ float g_obias[B_ * CO];

// ---------------- mma / ldmatrix helpers ----------------
__device__ __forceinline__ unsigned su32(const void* p) {
    return (unsigned)__cvta_generic_to_shared(p);
}
#define LDSM_X4(r, addr) \
    asm volatile("ldmatrix.sync.aligned.m8n8.x4.shared.b16 {%0,%1,%2,%3}, [%4];" \
        : "=r"((r)[0]), "=r"((r)[1]), "=r"((r)[2]), "=r"((r)[3]) : "r"(addr))
#define LDSM_X4T(r, addr) \
    asm volatile("ldmatrix.sync.aligned.m8n8.x4.trans.shared.b16 {%0,%1,%2,%3}, [%4];" \
        : "=r"((r)[0]), "=r"((r)[1]), "=r"((r)[2]), "=r"((r)[3]) : "r"(addr))
#define MMA_BF16(d, a, b0, b1) \
    asm volatile("mma.sync.aligned.m16n8k16.row.col.f32.bf16.bf16.f32 " \
        "{%0,%1,%2,%3}, {%4,%5,%6,%7}, {%8,%9}, {%0,%1,%2,%3};" \
        : "+f"((d)[0]), "+f"((d)[1]), "+f"((d)[2]), "+f"((d)[3]) \
        : "r"((a)[0]), "r"((a)[1]), "r"((a)[2]), "r"((a)[3]), "r"(b0), "r"(b1))

__device__ __forceinline__ unsigned packbf(__nv_bfloat16 lo, __nv_bfloat16 hi) {
    return ((unsigned)__bfloat16_as_ushort(hi) << 16) | __bfloat16_as_ushort(lo);
}
__device__ __forceinline__ void split4(float4 f, uint2 &hi, uint2 &lo) {
    __nv_bfloat16 hx = __float2bfloat16(f.x), hy = __float2bfloat16(f.y);
    __nv_bfloat16 hz = __float2bfloat16(f.z), hw = __float2bfloat16(f.w);
    __nv_bfloat16 lx = __float2bfloat16(f.x - __bfloat162float(hx));
    __nv_bfloat16 ly = __float2bfloat16(f.y - __bfloat162float(hy));
    __nv_bfloat16 lz = __float2bfloat16(f.z - __bfloat162float(hz));
    __nv_bfloat16 lw = __float2bfloat16(f.w - __bfloat162float(hw));
    hi.x = packbf(hx, hy); hi.y = packbf(hz, hw);
    lo.x = packbf(lx, ly); lo.y = packbf(lz, lw);
}

#define ASTR 72
#define BSTR 72

// ---------------- K1: 1x1 conv via bf16-split MMA (R9 champion form) --------
__global__ __launch_bounds__(256) void conv_mma_kernel(
    const float* __restrict__ xq, const float* __restrict__ xk,
    const float* __restrict__ xv,
    const float* __restrict__ Wk, const float* __restrict__ Wv,
    const float* __restrict__ bk, const float* __restrict__ bv)
{
    int which = blockIdx.z;
    const float* x    = (which == 0) ? xq : (which == 1) ? xk : xv;
    const float* W    = (which == 2) ? Wv : Wk;
    const float* bias = (which == 2) ? bv : bk;
    float* y          = (which == 0) ? g_yq : (which == 1) ? g_yk : g_yv;

    int bb = blockIdx.y;
    int n0 = blockIdx.x * 64;
    int tid = threadIdx.x;
    int lane = tid & 31, w = tid >> 5;
    int ct = (w & 3) * 16;
    int ng = (w >> 2) * 32;

    __shared__ __align__(16) __nv_bfloat16 Ah[64 * ASTR];
    __shared__ __align__(16) __nv_bfloat16 Al[64 * ASTR];
    __shared__ __align__(16) __nv_bfloat16 Bh[64 * BSTR];
    __shared__ __align__(16) __nv_bfloat16 Bl[64 * BSTR];

    int q = lane >> 3, rr = lane & 7;
    unsigned aOffH, aOffL, bOffH0, bOffL0, bOffH1, bOffL1;
    {
        int arow = ct + (q & 1) * 8 + rr;
        int acol = (q >> 1) * 8;
        aOffH = su32(Ah) + arow * (ASTR * 2) + acol * 2;
        aOffL = su32(Al) + arow * (ASTR * 2) + acol * 2;
        int brow = (q & 1) * 8 + rr;
        int bcol0 = ng + (q >> 1) * 8;
        int bcol1 = ng + 16 + (q >> 1) * 8;
        bOffH0 = su32(Bh) + brow * (BSTR * 2) + bcol0 * 2;
        bOffL0 = su32(Bl) + brow * (BSTR * 2) + bcol0 * 2;
        bOffH1 = su32(Bh) + brow * (BSTR * 2) + bcol1 * 2;
        bOffL1 = su32(Bl) + brow * (BSTR * 2) + bcol1 * 2;
    }

    float acc[4][4] = {};

    for (int s = 0; s < 2; s++) {
        #pragma unroll
        for (int i = 0; i < 4; i++) {
            int e = tid + i * 256;
            int co = e >> 4, ci4 = (e & 15) * 4;
            float4 f = *(const float4*)&W[co * CIN + s * 64 + ci4];
            uint2 hi, lo; split4(f, hi, lo);
            *(uint2*)&Ah[co * ASTR + ci4] = hi;
            *(uint2*)&Al[co * ASTR + ci4] = lo;
        }
        #pragma unroll
        for (int i = 0; i < 4; i++) {
            int e = tid + i * 256;
            int ci = e >> 4, nn4 = (e & 15) * 4;
            float4 f = *(const float4*)&x[((size_t)(bb * CIN + s * 64 + ci)) * N_ + n0 + nn4];
            uint2 hi, lo; split4(f, hi, lo);
            *(uint2*)&Bh[ci * BSTR + nn4] = hi;
            *(uint2*)&Bl[ci * BSTR + nn4] = lo;
        }
        __syncthreads();

        #pragma unroll
        for (int ks = 0; ks < 4; ks++) {
            unsigned aStep = ks * 32;
            unsigned bStep = ks * 16 * (BSTR * 2);
            unsigned ah[4], al[4], bh[4], bl[4], bh2[4], bl2[4];
            LDSM_X4(ah, aOffH + aStep);
            LDSM_X4(al, aOffL + aStep);
            LDSM_X4T(bh, bOffH0 + bStep);
            LDSM_X4T(bl, bOffL0 + bStep);
            LDSM_X4T(bh2, bOffH1 + bStep);
            LDSM_X4T(bl2, bOffL1 + bStep);
            MMA_BF16(acc[0], ah, bh[0], bh[1]);
            MMA_BF16(acc[0], ah, bl[0], bl[1]);
            MMA_BF16(acc[0], al, bh[0], bh[1]);
            MMA_BF16(acc[1], ah, bh[2], bh[3]);
            MMA_BF16(acc[1], ah, bl[2], bl[3]);
            MMA_BF16(acc[1], al, bh[2], bh[3]);
            MMA_BF16(acc[2], ah, bh2[0], bh2[1]);
            MMA_BF16(acc[2], ah, bl2[0], bl2[1]);
            MMA_BF16(acc[2], al, bh2[0], bh2[1]);
            MMA_BF16(acc[3], ah, bh2[2], bh2[3]);
            MMA_BF16(acc[3], ah, bl2[2], bl2[3]);
            MMA_BF16(acc[3], al, bh2[2], bh2[3]);
        }
        __syncthreads();
    }

    int r4 = lane >> 2, c2 = (lane & 3) * 2;
    int row0 = ct + r4, row1 = ct + r4 + 8;
    float b0v = bias[row0], b1v = bias[row1];
    #pragma unroll
    for (int t = 0; t < 4; t++) {
        int col = n0 + ng + t * 8 + c2;
        *(float2*)&y[((size_t)(bb * 64 + row0)) * N_ + col] =
            make_float2(acc[t][0] + b0v, acc[t][1] + b0v);
        *(float2*)&y[((size_t)(bb * 64 + row1)) * N_ + col] =
            make_float2(acc[t][2] + b1v, acc[t][3] + b1v);
    }
}

// ---------------- K2: BN batch stats (R9 form) ----------------
__global__ __launch_bounds__(256) void bn_stats_kernel(
    const float* __restrict__ gamma, const float* __restrict__ beta)
{
    int c = blockIdx.x & 63;
    int which = blockIdx.x >> 6;
    const float* y = which ? g_yk : g_yq;
    int tid = threadIdx.x;

    float s = 0.f, ss = 0.f;
    #pragma unroll
    for (int b = 0; b < B_; b++) {
        const float4* row = (const float4*)(y + ((size_t)(b * 64 + c)) * N_);
        #pragma unroll
        for (int i = 0; i < 4; i++) {
            float4 f = row[tid + i * 256];
            s  += f.x + f.y + f.z + f.w;
            ss += f.x * f.x + f.y * f.y + f.z * f.z + f.w * f.w;
        }
    }
    #pragma unroll
    for (int o = 16; o; o >>= 1) {
        s  += __shfl_down_sync(0xffffffffu, s, o);
        ss += __shfl_down_sync(0xffffffffu, ss, o);
    }
    __shared__ float rs[8], rss[8];
    int wid = tid >> 5, lane = tid & 31;
    if (lane == 0) { rs[wid] = s; rss[wid] = ss; }
    __syncthreads();
    if (tid == 0) {
        float S = 0.f, SS = 0.f;
        #pragma unroll
        for (int i = 0; i < 8; i++) { S += rs[i]; SS += rss[i]; }
        const float inv = 1.0f / 32768.0f;
        float mean = S * inv;
        float var  = SS * inv - mean * mean;
        float sc = gamma[c] * rsqrtf(var + 1e-5f);
        g_scale[blockIdx.x] = sc;
        g_shift[blockIdx.x] = beta[c] - mean * sc;
    }
}

// ---------------- K3: apply BN + L2-normalize (R9 form) ----------------
__global__ __launch_bounds__(256) void norm_kernel() {
    int colblk = blockIdx.x;
    int which = colblk >> 8;
    int r = colblk & 255;
    int b = r >> 5;
    int n0 = (r & 31) * 128;
    float* y = which ? g_yk : g_yq;
    int tid = threadIdx.x;
    int half = tid >> 7;
    int l = tid & 127;
    int n = n0 + l;

    __shared__ float scs[64], shs[64], ss2[2][128];
    if (tid < 64) {
        scs[tid] = g_scale[which * 64 + tid];
        shs[tid] = g_shift[which * 64 + tid];
    }
    __syncthreads();

    float v[32];
    float ss = 0.f;
    #pragma unroll
    for (int i = 0; i < 32; i++) {
        int c = half * 32 + i;
        float t = y[((size_t)(b * 64 + c)) * N_ + n] * scs[c] + shs[c];
        v[i] = t; ss += t * t;
    }
    ss2[half][l] = ss;
    __syncthreads();
    float rn = 1.0f / (sqrtf(ss2[0][l] + ss2[1][l]) + 1e-7f);
    #pragma unroll
    for (int i = 0; i < 32; i++)
        y[((size_t)(b * 64 + half * 32 + i)) * N_ + n] = v[i] * rn;
}

// ---------------- K4: KV via bf16-split MMA (64 chunks, single tile) ---------
// grid (KVCHUNKS=64, B_), 256 threads. A=K[ck][n], B=V[cv][n] plain LDSM.
__global__ __launch_bounds__(256) void kv_mma_kernel() {
    int chunk = blockIdx.x, b = blockIdx.y;
    int tid = threadIdx.x;
    int lane = tid & 31, w = tid >> 5;
    int ct = (w & 3) * 16;
    int cg = (w >> 2) * 32;

    __shared__ __align__(16) __nv_bfloat16 Kh[64 * ASTR];
    __shared__ __align__(16) __nv_bfloat16 Kl[64 * ASTR];
    __shared__ __align__(16) __nv_bfloat16 Vh[64 * ASTR];
    __shared__ __align__(16) __nv_bfloat16 Vl[64 * ASTR];
    __shared__ float vps[64][4];

    int q = lane >> 3, rr = lane & 7;
    unsigned aH, aL, bH0, bL0, bH1, bL1;
    {
        int arow = ct + (q & 1) * 8 + rr;
        int acol = (q >> 1) * 8;
        aH = su32(Kh) + arow * (ASTR * 2) + acol * 2;
        aL = su32(Kl) + arow * (ASTR * 2) + acol * 2;
        int brow = cg + (q >> 1) * 8 + rr;
        int bcol = (q & 1) * 8;
        bH0 = su32(Vh) + brow * (ASTR * 2) + bcol * 2;
        bL0 = su32(Vl) + brow * (ASTR * 2) + bcol * 2;
        bH1 = bH0 + 16 * (ASTR * 2);
        bL1 = bL0 + 16 * (ASTR * 2);
    }

    int cc = tid & 63, q4 = tid >> 6;
    float acc[4][4] = {};

    int n0 = chunk * 64;
    #pragma unroll
    for (int i = 0; i < 4; i++) {
        int e = tid + i * 256;
        int row = e >> 4, nn4 = (e & 15) * 4;
        float4 fk = *(const float4*)&g_yk[((size_t)(b * 64 + row)) * N_ + n0 + nn4];
        float4 fv = *(const float4*)&g_yv[((size_t)(b * 64 + row)) * N_ + n0 + nn4];
        uint2 hi, lo;
        split4(fk, hi, lo);
        *(uint2*)&Kh[row * ASTR + nn4] = hi;
        *(uint2*)&Kl[row * ASTR + nn4] = lo;
        split4(fv, hi, lo);
        *(uint2*)&Vh[row * ASTR + nn4] = hi;
        *(uint2*)&Vl[row * ASTR + nn4] = lo;
    }
    __syncthreads();

    #pragma unroll
    for (int ks = 0; ks < 4; ks++) {
        unsigned step = ks * 32;
        unsigned ah[4], al[4], bh[4], bl[4], bh2[4], bl2[4];
        LDSM_X4(ah, aH + step);
        LDSM_X4(al, aL + step);
        LDSM_X4(bh, bH0 + step);
        LDSM_X4(bl, bL0 + step);
        LDSM_X4(bh2, bH1 + step);
        LDSM_X4(bl2, bL1 + step);
        MMA_BF16(acc[0], ah, bh[0], bh[1]);
        MMA_BF16(acc[0], ah, bl[0], bl[1]);
        MMA_BF16(acc[0], al, bh[0], bh[1]);
        MMA_BF16(acc[1], ah, bh[2], bh[3]);
        MMA_BF16(acc[1], ah, bl[2], bl[3]);
        MMA_BF16(acc[1], al, bh[2], bh[3]);
        MMA_BF16(acc[2], ah, bh2[0], bh2[1]);
        MMA_BF16(acc[2], ah, bl2[0], bl2[1]);
        MMA_BF16(acc[2], al, bh2[0], bh2[1]);
        MMA_BF16(acc[3], ah, bh2[2], bh2[3]);
        MMA_BF16(acc[3], ah, bl2[2], bl2[3]);
        MMA_BF16(acc[3], al, bh2[2], bh2[3]);
    }

    // fused V row sums (hi+lo) from smem bf16
    float vp = 0.f;
    #pragma unroll
    for (int i = 0; i < 16; i++) {
        int idx = cc * ASTR + q4 * 16 + i;
        vp += __bfloat162float(Vh[idx]) + __bfloat162float(Vl[idx]);
    }

    int r4 = lane >> 2, c2 = (lane & 3) * 2;
    int row0 = ct + r4, row1 = ct + r4 + 8;
    float* base = &g_kvpart[(((size_t)chunk * B_ + b)) * 4096];
    #pragma unroll
    for (int t = 0; t < 4; t++) {
        int col = cg + t * 8 + c2;
        *(float2*)&base[row0 * 64 + col] = make_float2(acc[t][0], acc[t][1]);
        *(float2*)&base[row1 * 64 + col] = make_float2(acc[t][2], acc[t][3]);
    }

    vps[cc][q4] = vp;
    __syncthreads();
    if (tid < 64)
        g_vsumpart[((size_t)chunk * B_ + b) * 64 + tid] =
            vps[tid][0] + vps[tid][1] + vps[tid][2] + vps[tid][3];
}

// ---------------- K5: M^T = (KV @ Ww^T)^T; obias (64-chunk reduce) -----------
__global__ __launch_bounds__(256) void m_kernel(
    const float* __restrict__ Ww, const float* __restrict__ bw)
{
    int b = blockIdx.x;
    __shared__ float KVs[64][64];
    __shared__ float WwT[64][128];
    __shared__ float vs_s[64];
    int tid = threadIdx.x;

    if (tid < 64) {
        float S = 0.f;
        #pragma unroll
        for (int c2 = 0; c2 < KVCHUNKS; c2++)
            S += g_vsumpart[((size_t)c2 * B_ + b) * 64 + tid];
        vs_s[tid] = S;
    }
    for (int e = tid; e < 4096; e += 256) {
        float s = 0.f;
        #pragma unroll 16
        for (int c2 = 0; c2 < KVCHUNKS; c2++)
            s += g_kvpart[((size_t)c2 * B_ + b) * 4096 + e];
        KVs[e >> 6][e & 63] = s;
    }
    for (int e = tid; e < 8192; e += 256) {
        int cv = e >> 7, co = e & 127;
        WwT[cv][co] = Ww[co * CV + cv];
    }
    __syncthreads();

    int co = tid & 127;
    for (int ck = (tid >> 7); ck < 64; ck += 2) {
        float s = 0.f;
        #pragma unroll 8
        for (int cv = 0; cv < 64; cv++) s += KVs[ck][cv] * WwT[cv][co];
        g_M[((size_t)b * 128 + co) * 64 + ck] = s;
    }
    if (tid < 128) {
        float s = bw[tid];
        #pragma unroll 8
        for (int cv = 0; cv < 64; cv++) s += vs_s[cv] * WwT[cv][tid];
        g_obias[b * CO + tid] = s;
    }
}

// ---------------- K6: out via bf16-split MMA (R9 form) -----------------------
__global__ __launch_bounds__(256) void out_mma_kernel(float* __restrict__ out) {
    int b = blockIdx.y, n0 = blockIdx.x * 64, ch = blockIdx.z;
    int co0 = ch * 64;
    int tid = threadIdx.x;
    int lane = tid & 31, w = tid >> 5;
    int ct = (w & 3) * 16;
    int ng = (w >> 2) * 32;

    __shared__ __align__(16) __nv_bfloat16 Ah[64 * ASTR];
    __shared__ __align__(16) __nv_bfloat16 Al[64 * ASTR];
    __shared__ __align__(16) __nv_bfloat16 Bh[64 * BSTR];
    __shared__ __align__(16) __nv_bfloat16 Bl[64 * BSTR];

    int q = lane >> 3, rr = lane & 7;
    unsigned aOffH, aOffL, bOffH0, bOffL0, bOffH1, bOffL1;
    {
        int arow = ct + (q & 1) * 8 + rr;
        int acol = (q >> 1) * 8;
        aOffH = su32(Ah) + arow * (ASTR * 2) + acol * 2;
        aOffL = su32(Al) + arow * (ASTR * 2) + acol * 2;
        int brow = (q & 1) * 8 + rr;
        int bcol0 = ng + (q >> 1) * 8;
        int bcol1 = ng + 16 + (q >> 1) * 8;
        bOffH0 = su32(Bh) + brow * (BSTR * 2) + bcol0 * 2;
        bOffL0 = su32(Bl) + brow * (BSTR * 2) + bcol0 * 2;
        bOffH1 = su32(Bh) + brow * (BSTR * 2) + bcol1 * 2;
        bOffL1 = su32(Bl) + brow * (BSTR * 2) + bcol1 * 2;
    }

    #pragma unroll
    for (int i = 0; i < 4; i++) {
        int e = tid + i * 256;
        int row = e >> 4, ck4 = (e & 15) * 4;
        float4 f = *(const float4*)&g_M[((size_t)b * 128 + co0 + row) * 64 + ck4];
        uint2 hi, lo; split4(f, hi, lo);
        *(uint2*)&Ah[row * ASTR + ck4] = hi;
        *(uint2*)&Al[row * ASTR + ck4] = lo;
    }
    #pragma unroll
    for (int i = 0; i < 4; i++) {
        int e = tid + i * 256;
        int ck = e >> 4, nn4 = (e & 15) * 4;
        float4 f = *(const float4*)&g_yq[((size_t)(b * 64 + ck)) * N_ + n0 + nn4];
        uint2 hi, lo; split4(f, hi, lo);
        *(uint2*)&Bh[ck * BSTR + nn4] = hi;
        *(uint2*)&Bl[ck * BSTR + nn4] = lo;
    }
    __syncthreads();

    float acc[4][4] = {};
    #pragma unroll
    for (int ks = 0; ks < 4; ks++) {
        unsigned aStep = ks * 32;
        unsigned bStep = ks * 16 * (BSTR * 2);
        unsigned ah[4], al[4], bh[4], bl[4], bh2[4], bl2[4];
        LDSM_X4(ah, aOffH + aStep);
        LDSM_X4(al, aOffL + aStep);
        LDSM_X4T(bh, bOffH0 + bStep);
        LDSM_X4T(bl, bOffL0 + bStep);
        LDSM_X4T(bh2, bOffH1 + bStep);
        LDSM_X4T(bl2, bOffL1 + bStep);
        MMA_BF16(acc[0], ah, bh[0], bh[1]);
        MMA_BF16(acc[0], ah, bl[0], bl[1]);
        MMA_BF16(acc[0], al, bh[0], bh[1]);
        MMA_BF16(acc[1], ah, bh[2], bh[3]);
        MMA_BF16(acc[1], ah, bl[2], bl[3]);
        MMA_BF16(acc[1], al, bh[2], bh[3]);
        MMA_BF16(acc[2], ah, bh2[0], bh2[1]);
        MMA_BF16(acc[2], ah, bl2[0], bl2[1]);
        MMA_BF16(acc[2], al, bh2[0], bh2[1]);
        MMA_BF16(acc[3], ah, bh2[2], bh2[3]);
        MMA_BF16(acc[3], ah, bl2[2], bl2[3]);
        MMA_BF16(acc[3], al, bh2[2], bh2[3]);
    }

    int r4 = lane >> 2, c2 = (lane & 3) * 2;
    int row0 = co0 + ct + r4, row1 = row0 + 8;
    float b0v = g_obias[b * CO + row0], b1v = g_obias[b * CO + row1];
    #pragma unroll
    for (int t = 0; t < 4; t++) {
        int col = n0 + ng + t * 8 + c2;
        *(float2*)&out[((size_t)(b * CO + row0)) * N_ + col] =
            make_float2(acc[t][0] + b0v, acc[t][1] + b0v);
        *(float2*)&out[((size_t)(b * CO + row1)) * N_ + col] =
            make_float2(acc[t][2] + b1v, acc[t][3] + b1v);
    }
}

// ---------------- launch ----------------
extern "C" void kernel_launch(void* const* d_in, const int* in_sizes, int n_in,
                              void* d_out, int out_size) {
    const float* q     = (const float*)d_in[0];
    const float* k     = (const float*)d_in[1];
    const float* v     = (const float*)d_in[2];
    const float* Wk    = (const float*)d_in[3];
    const float* bk    = (const float*)d_in[4];
    const float* gamma = (const float*)d_in[5];
    const float* beta  = (const float*)d_in[6];
    const float* Wv    = (const float*)d_in[7];
    const float* bv    = (const float*)d_in[8];
    const float* Ww    = (const float*)d_in[9];
    const float* bw    = (const float*)d_in[10];
    float* out = (float*)d_out;

    conv_mma_kernel<<<dim3(64, B_, 3), 256>>>(q, k, v, Wk, Wv, bk, bv);
    bn_stats_kernel<<<128, 256>>>(gamma, beta);
    norm_kernel<<<512, 256>>>();
    kv_mma_kernel<<<dim3(KVCHUNKS, B_), 256>>>();
    m_kernel<<<B_, 256>>>(Ww, bw);
    out_mma_kernel<<<dim3(64, B_, 2), 256>>>(out);
}

// round 12
// speedup vs baseline: 1.7013x; 1.1902x over previous
#include <cuda_runtime.h>
#include <cuda_bf16.h>
#include <math.h>

#define B_   8
#define CIN  128
#define CK   64
#define CV   64
#define CO   128
#define N_   4096
#define KVCHUNKS 32

// ---------------- scratch ----------------
__device__ float g_yq[B_ * CK * N_];
__device__ float g_yk[B_ * CK * N_];
__device__ float g_yv[B_ * CV * N_];
__device__ float g_scale[2 * CK];
__device__ float g_shift[2 * CK];
__device__ float g_vsumpart[KVCHUNKS * B_ * CV];
__device__ float g_kvpart[KVCHUNKS * B_ * CK * CV];
__device__ float g_M[B_ * CO * CK];      // TRANSPOSED: [b][co][ck]
__device__ float g_obias[B_ * CO];

// ---------------- mma / ldmatrix helpers ----------------
__device__ __forceinline__ unsigned su32(const void* p) {
    return (unsigned)__cvta_generic_to_shared(p);
}
#define LDSM_X4(r, addr) \
    asm volatile("ldmatrix.sync.aligned.m8n8.x4.shared.b16 {%0,%1,%2,%3}, [%4];" \
        : "=r"((r)[0]), "=r"((r)[1]), "=r"((r)[2]), "=r"((r)[3]) : "r"(addr))
#define LDSM_X4T(r, addr) \
    asm volatile("ldmatrix.sync.aligned.m8n8.x4.trans.shared.b16 {%0,%1,%2,%3}, [%4];" \
        : "=r"((r)[0]), "=r"((r)[1]), "=r"((r)[2]), "=r"((r)[3]) : "r"(addr))
#define MMA_BF16(d, a, b0, b1) \
    asm volatile("mma.sync.aligned.m16n8k16.row.col.f32.bf16.bf16.f32 " \
        "{%0,%1,%2,%3}, {%4,%5,%6,%7}, {%8,%9}, {%0,%1,%2,%3};" \
        : "+f"((d)[0]), "+f"((d)[1]), "+f"((d)[2]), "+f"((d)[3]) \
        : "r"((a)[0]), "r"((a)[1]), "r"((a)[2]), "r"((a)[3]), "r"(b0), "r"(b1))

__device__ __forceinline__ unsigned packbf(__nv_bfloat16 lo, __nv_bfloat16 hi) {
    return ((unsigned)__bfloat16_as_ushort(hi) << 16) | __bfloat16_as_ushort(lo);
}
__device__ __forceinline__ void split4(float4 f, uint2 &hi, uint2 &lo) {
    __nv_bfloat16 hx = __float2bfloat16(f.x), hy = __float2bfloat16(f.y);
    __nv_bfloat16 hz = __float2bfloat16(f.z), hw = __float2bfloat16(f.w);
    __nv_bfloat16 lx = __float2bfloat16(f.x - __bfloat162float(hx));
    __nv_bfloat16 ly = __float2bfloat16(f.y - __bfloat162float(hy));
    __nv_bfloat16 lz = __float2bfloat16(f.z - __bfloat162float(hz));
    __nv_bfloat16 lw = __float2bfloat16(f.w - __bfloat162float(hw));
    hi.x = packbf(hx, hy); hi.y = packbf(hz, hw);
    lo.x = packbf(lx, ly); lo.y = packbf(lz, lw);
}

#define ASTR 72
#define BSTR 72

// ---------------- K1: 1x1 conv via bf16-split MMA ----------------------------
__global__ __launch_bounds__(256) void conv_mma_kernel(
    const float* __restrict__ xq, const float* __restrict__ xk,
    const float* __restrict__ xv,
    const float* __restrict__ Wk, const float* __restrict__ Wv,
    const float* __restrict__ bk, const float* __restrict__ bv)
{
    int which = blockIdx.z;
    const float* x    = (which == 0) ? xq : (which == 1) ? xk : xv;
    const float* W    = (which == 2) ? Wv : Wk;
    const float* bias = (which == 2) ? bv : bk;
    float* y          = (which == 0) ? g_yq : (which == 1) ? g_yk : g_yv;

    int bb = blockIdx.y;
    int n0 = blockIdx.x * 64;
    int tid = threadIdx.x;
    int lane = tid & 31, w = tid >> 5;
    int ct = (w & 3) * 16;
    int ng = (w >> 2) * 32;

    __shared__ __align__(16) __nv_bfloat16 Ah[64 * ASTR];
    __shared__ __align__(16) __nv_bfloat16 Al[64 * ASTR];
    __shared__ __align__(16) __nv_bfloat16 Bh[64 * BSTR];
    __shared__ __align__(16) __nv_bfloat16 Bl[64 * BSTR];

    int q = lane >> 3, rr = lane & 7;
    unsigned aOffH, aOffL, bOffH0, bOffL0, bOffH1, bOffL1;
    {
        int arow = ct + (q & 1) * 8 + rr;
        int acol = (q >> 1) * 8;
        aOffH = su32(Ah) + arow * (ASTR * 2) + acol * 2;
        aOffL = su32(Al) + arow * (ASTR * 2) + acol * 2;
        int brow = (q & 1) * 8 + rr;
        int bcol0 = ng + (q >> 1) * 8;
        int bcol1 = ng + 16 + (q >> 1) * 8;
        bOffH0 = su32(Bh) + brow * (BSTR * 2) + bcol0 * 2;
        bOffL0 = su32(Bl) + brow * (BSTR * 2) + bcol0 * 2;
        bOffH1 = su32(Bh) + brow * (BSTR * 2) + bcol1 * 2;
        bOffL1 = su32(Bl) + brow * (BSTR * 2) + bcol1 * 2;
    }

    float acc[4][4] = {};

    for (int s = 0; s < 2; s++) {
        #pragma unroll
        for (int i = 0; i < 4; i++) {
            int e = tid + i * 256;
            int co = e >> 4, ci4 = (e & 15) * 4;
            float4 f = *(const float4*)&W[co * CIN + s * 64 + ci4];
            uint2 hi, lo; split4(f, hi, lo);
            *(uint2*)&Ah[co * ASTR + ci4] = hi;
            *(uint2*)&Al[co * ASTR + ci4] = lo;
        }
        #pragma unroll
        for (int i = 0; i < 4; i++) {
            int e = tid + i * 256;
            int ci = e >> 4, nn4 = (e & 15) * 4;
            float4 f = *(const float4*)&x[((size_t)(bb * CIN + s * 64 + ci)) * N_ + n0 + nn4];
            uint2 hi, lo; split4(f, hi, lo);
            *(uint2*)&Bh[ci * BSTR + nn4] = hi;
            *(uint2*)&Bl[ci * BSTR + nn4] = lo;
        }
        __syncthreads();

        #pragma unroll
        for (int ks = 0; ks < 4; ks++) {
            unsigned aStep = ks * 32;
            unsigned bStep = ks * 16 * (BSTR * 2);
            unsigned ah[4], al[4], bh[4], bl[4], bh2[4], bl2[4];
            LDSM_X4(ah, aOffH + aStep);
            LDSM_X4(al, aOffL + aStep);
            LDSM_X4T(bh, bOffH0 + bStep);
            LDSM_X4T(bl, bOffL0 + bStep);
            LDSM_X4T(bh2, bOffH1 + bStep);
            LDSM_X4T(bl2, bOffL1 + bStep);
            MMA_BF16(acc[0], ah, bh[0], bh[1]);
            MMA_BF16(acc[0], ah, bl[0], bl[1]);
            MMA_BF16(acc[0], al, bh[0], bh[1]);
            MMA_BF16(acc[1], ah, bh[2], bh[3]);
            MMA_BF16(acc[1], ah, bl[2], bl[3]);
            MMA_BF16(acc[1], al, bh[2], bh[3]);
            MMA_BF16(acc[2], ah, bh2[0], bh2[1]);
            MMA_BF16(acc[2], ah, bl2[0], bl2[1]);
            MMA_BF16(acc[2], al, bh2[0], bh2[1]);
            MMA_BF16(acc[3], ah, bh2[2], bh2[3]);
            MMA_BF16(acc[3], ah, bl2[2], bl2[3]);
            MMA_BF16(acc[3], al, bh2[2], bh2[3]);
        }
        __syncthreads();
    }

    int r4 = lane >> 2, c2 = (lane & 3) * 2;
    int row0 = ct + r4, row1 = ct + r4 + 8;
    float b0v = bias[row0], b1v = bias[row1];
    #pragma unroll
    for (int t = 0; t < 4; t++) {
        int col = n0 + ng + t * 8 + c2;
        *(float2*)&y[((size_t)(bb * 64 + row0)) * N_ + col] =
            make_float2(acc[t][0] + b0v, acc[t][1] + b0v);
        *(float2*)&y[((size_t)(bb * 64 + row1)) * N_ + col] =
            make_float2(acc[t][2] + b1v, acc[t][3] + b1v);
    }
}

// ---------------- K2: BN batch stats ----------------
__global__ __launch_bounds__(256) void bn_stats_kernel(
    const float* __restrict__ gamma, const float* __restrict__ beta)
{
    int c = blockIdx.x & 63;
    int which = blockIdx.x >> 6;
    const float* y = which ? g_yk : g_yq;
    int tid = threadIdx.x;

    float s = 0.f, ss = 0.f;
    #pragma unroll
    for (int b = 0; b < B_; b++) {
        const float4* row = (const float4*)(y + ((size_t)(b * 64 + c)) * N_);
        #pragma unroll
        for (int i = 0; i < 4; i++) {
            float4 f = row[tid + i * 256];
            s  += f.x + f.y + f.z + f.w;
            ss += f.x * f.x + f.y * f.y + f.z * f.z + f.w * f.w;
        }
    }
    #pragma unroll
    for (int o = 16; o; o >>= 1) {
        s  += __shfl_down_sync(0xffffffffu, s, o);
        ss += __shfl_down_sync(0xffffffffu, ss, o);
    }
    __shared__ float rs[8], rss[8];
    int wid = tid >> 5, lane = tid & 31;
    if (lane == 0) { rs[wid] = s; rss[wid] = ss; }
    __syncthreads();
    if (tid == 0) {
        float S = 0.f, SS = 0.f;
        #pragma unroll
        for (int i = 0; i < 8; i++) { S += rs[i]; SS += rss[i]; }
        const float inv = 1.0f / 32768.0f;
        float mean = S * inv;
        float var  = SS * inv - mean * mean;
        float sc = gamma[c] * rsqrtf(var + 1e-5f);
        g_scale[blockIdx.x] = sc;
        g_shift[blockIdx.x] = beta[c] - mean * sc;
    }
}

// ---------------- K3: apply BN + L2-normalize (float2, 16ch x 2col/thread) ---
// grid 256, 512 threads; block covers 256 columns of one (which,b).
__global__ __launch_bounds__(512) void norm_kernel() {
    int blk = blockIdx.x;
    int which = blk >> 7;
    int r = blk & 127;
    int b = r >> 4;
    int n0 = (r & 15) * 256;
    float* y = which ? g_yk : g_yq;
    int tid = threadIdx.x;
    int qt = tid >> 7;           // channel quarter 0..3
    int l = tid & 127;
    int n = n0 + l * 2;

    __shared__ float scs[64], shs[64];
    __shared__ float ss4[4][256];
    if (tid < 64) {
        scs[tid] = g_scale[which * 64 + tid];
        shs[tid] = g_shift[which * 64 + tid];
    }
    __syncthreads();

    float2 v[16];
    float ssa = 0.f, ssb = 0.f;
    #pragma unroll
    for (int i = 0; i < 16; i++) {
        int c = qt * 16 + i;
        float2 t = *(const float2*)&y[((size_t)(b * 64 + c)) * N_ + n];
        t.x = t.x * scs[c] + shs[c];
        t.y = t.y * scs[c] + shs[c];
        v[i] = t;
        ssa += t.x * t.x;  ssb += t.y * t.y;
    }
    ss4[qt][l * 2] = ssa;  ss4[qt][l * 2 + 1] = ssb;
    __syncthreads();
    float rna = 1.0f / (sqrtf(ss4[0][l*2]   + ss4[1][l*2]   + ss4[2][l*2]   + ss4[3][l*2])   + 1e-7f);
    float rnb = 1.0f / (sqrtf(ss4[0][l*2+1] + ss4[1][l*2+1] + ss4[2][l*2+1] + ss4[3][l*2+1]) + 1e-7f);
    #pragma unroll
    for (int i = 0; i < 16; i++) {
        int c = qt * 16 + i;
        *(float2*)&y[((size_t)(b * 64 + c)) * N_ + n] = make_float2(v[i].x * rna, v[i].y * rnb);
    }
}

// ---------------- K4: KV via bf16-split MMA + fused vsum partials ------------
// grid (KVCHUNKS=32, B_), 256 threads.
__global__ __launch_bounds__(256) void kv_mma_kernel() {
    int chunk = blockIdx.x, b = blockIdx.y;
    int tid = threadIdx.x;
    int lane = tid & 31, w = tid >> 5;
    int ct = (w & 3) * 16;
    int cg = (w >> 2) * 32;

    __shared__ __align__(16) __nv_bfloat16 Kh[64 * ASTR];
    __shared__ __align__(16) __nv_bfloat16 Kl[64 * ASTR];
    __shared__ __align__(16) __nv_bfloat16 Vh[64 * ASTR];
    __shared__ __align__(16) __nv_bfloat16 Vl[64 * ASTR];
    __shared__ float vps[64][4];

    int q = lane >> 3, rr = lane & 7;
    unsigned aH, aL, bH0, bL0, bH1, bL1;
    {
        int arow = ct + (q & 1) * 8 + rr;
        int acol = (q >> 1) * 8;
        aH = su32(Kh) + arow * (ASTR * 2) + acol * 2;
        aL = su32(Kl) + arow * (ASTR * 2) + acol * 2;
        int brow = cg + (q >> 1) * 8 + rr;
        int bcol = (q & 1) * 8;
        bH0 = su32(Vh) + brow * (ASTR * 2) + bcol * 2;
        bL0 = su32(Vl) + brow * (ASTR * 2) + bcol * 2;
        bH1 = bH0 + 16 * (ASTR * 2);
        bL1 = bL0 + 16 * (ASTR * 2);
    }

    int cc = tid & 63, q4 = tid >> 6;
    float acc[4][4] = {};
    float vp = 0.f;

    for (int t = 0; t < 2; t++) {
        int n0 = chunk * 128 + t * 64;
        #pragma unroll
        for (int i = 0; i < 4; i++) {
            int e = tid + i * 256;
            int row = e >> 4, nn4 = (e & 15) * 4;
            float4 fk = *(const float4*)&g_yk[((size_t)(b * 64 + row)) * N_ + n0 + nn4];
            float4 fv = *(const float4*)&g_yv[((size_t)(b * 64 + row)) * N_ + n0 + nn4];
            uint2 hi, lo;
            split4(fk, hi, lo);
            *(uint2*)&Kh[row * ASTR + nn4] = hi;
            *(uint2*)&Kl[row * ASTR + nn4] = lo;
            split4(fv, hi, lo);
            *(uint2*)&Vh[row * ASTR + nn4] = hi;
            *(uint2*)&Vl[row * ASTR + nn4] = lo;
        }
        __syncthreads();

        #pragma unroll
        for (int ks = 0; ks < 4; ks++) {
            unsigned step = ks * 32;
            unsigned ah[4], al[4], bh[4], bl[4], bh2[4], bl2[4];
            LDSM_X4(ah, aH + step);
            LDSM_X4(al, aL + step);
            LDSM_X4(bh, bH0 + step);
            LDSM_X4(bl, bL0 + step);
            LDSM_X4(bh2, bH1 + step);
            LDSM_X4(bl2, bL1 + step);
            MMA_BF16(acc[0], ah, bh[0], bh[1]);
            MMA_BF16(acc[0], ah, bl[0], bl[1]);
            MMA_BF16(acc[0], al, bh[0], bh[1]);
            MMA_BF16(acc[1], ah, bh[2], bh[3]);
            MMA_BF16(acc[1], ah, bl[2], bl[3]);
            MMA_BF16(acc[1], al, bh[2], bh[3]);
            MMA_BF16(acc[2], ah, bh2[0], bh2[1]);
            MMA_BF16(acc[2], ah, bl2[0], bl2[1]);
            MMA_BF16(acc[2], al, bh2[0], bh2[1]);
            MMA_BF16(acc[3], ah, bh2[2], bh2[3]);
            MMA_BF16(acc[3], ah, bl2[2], bl2[3]);
            MMA_BF16(acc[3], al, bh2[2], bh2[3]);
        }
        // fused V row sums (hi+lo) from smem bf16
        #pragma unroll
        for (int i = 0; i < 16; i++) {
            int idx = cc * ASTR + q4 * 16 + i;
            vp += __bfloat162float(Vh[idx]) + __bfloat162float(Vl[idx]);
        }
        __syncthreads();
    }

    int r4 = lane >> 2, c2 = (lane & 3) * 2;
    int row0 = ct + r4, row1 = ct + r4 + 8;
    float* base = &g_kvpart[(((size_t)chunk * B_ + b)) * 4096];
    #pragma unroll
    for (int t = 0; t < 4; t++) {
        int col = cg + t * 8 + c2;
        *(float2*)&base[row0 * 64 + col] = make_float2(acc[t][0], acc[t][1]);
        *(float2*)&base[row1 * 64 + col] = make_float2(acc[t][2], acc[t][3]);
    }

    vps[cc][q4] = vp;
    __syncthreads();
    if (tid < 64)
        g_vsumpart[((size_t)chunk * B_ + b) * 64 + tid] =
            vps[tid][0] + vps[tid][1] + vps[tid][2] + vps[tid][3];
}

// ---------------- K5: M^T = (KV @ Ww^T)^T; obias ----------------------------
__global__ __launch_bounds__(256) void m_kernel(
    const float* __restrict__ Ww, const float* __restrict__ bw)
{
    int b = blockIdx.x;
    __shared__ float KVs[64][64];
    __shared__ float WwT[64][128];
    __shared__ float vs_s[64];
    int tid = threadIdx.x;

    if (tid < 64) {
        float S = 0.f;
        #pragma unroll
        for (int c2 = 0; c2 < KVCHUNKS; c2++)
            S += g_vsumpart[((size_t)c2 * B_ + b) * 64 + tid];
        vs_s[tid] = S;
    }
    for (int e = tid; e < 4096; e += 256) {
        float s = 0.f;
        #pragma unroll
        for (int c2 = 0; c2 < KVCHUNKS; c2++)
            s += g_kvpart[((size_t)c2 * B_ + b) * 4096 + e];
        KVs[e >> 6][e & 63] = s;
    }
    for (int e = tid; e < 8192; e += 256) {
        int cv = e >> 7, co = e & 127;
        WwT[cv][co] = Ww[co * CV + cv];
    }
    __syncthreads();

    int co = tid & 127;
    for (int ck = (tid >> 7); ck < 64; ck += 2) {
        float s = 0.f;
        #pragma unroll 8
        for (int cv = 0; cv < 64; cv++) s += KVs[ck][cv] * WwT[cv][co];
        g_M[((size_t)b * 128 + co) * 64 + ck] = s;
    }
    if (tid < 128) {
        float s = bw[tid];
        #pragma unroll 8
        for (int cv = 0; cv < 64; cv++) s += vs_s[cv] * WwT[cv][tid];
        g_obias[b * CO + tid] = s;
    }
}

// ---------------- K6: out via bf16-split MMA ---------------------------------
__global__ __launch_bounds__(256) void out_mma_kernel(float* __restrict__ out) {
    int b = blockIdx.y, n0 = blockIdx.x * 64, ch = blockIdx.z;
    int co0 = ch * 64;
    int tid = threadIdx.x;
    int lane = tid & 31, w = tid >> 5;
    int ct = (w & 3) * 16;
    int ng = (w >> 2) * 32;

    __shared__ __align__(16) __nv_bfloat16 Ah[64 * ASTR];
    __shared__ __align__(16) __nv_bfloat16 Al[64 * ASTR];
    __shared__ __align__(16) __nv_bfloat16 Bh[64 * BSTR];
    __shared__ __align__(16) __nv_bfloat16 Bl[64 * BSTR];

    int q = lane >> 3, rr = lane & 7;
    unsigned aOffH, aOffL, bOffH0, bOffL0, bOffH1, bOffL1;
    {
        int arow = ct + (q & 1) * 8 + rr;
        int acol = (q >> 1) * 8;
        aOffH = su32(Ah) + arow * (ASTR * 2) + acol * 2;
        aOffL = su32(Al) + arow * (ASTR * 2) + acol * 2;
        int brow = (q & 1) * 8 + rr;
        int bcol0 = ng + (q >> 1) * 8;
        int bcol1 = ng + 16 + (q >> 1) * 8;
        bOffH0 = su32(Bh) + brow * (BSTR * 2) + bcol0 * 2;
        bOffL0 = su32(Bl) + brow * (BSTR * 2) + bcol0 * 2;
        bOffH1 = su32(Bh) + brow * (BSTR * 2) + bcol1 * 2;
        bOffL1 = su32(Bl) + brow * (BSTR * 2) + bcol1 * 2;
    }

    #pragma unroll
    for (int i = 0; i < 4; i++) {
        int e = tid + i * 256;
        int row = e >> 4, ck4 = (e & 15) * 4;
        float4 f = *(const float4*)&g_M[((size_t)b * 128 + co0 + row) * 64 + ck4];
        uint2 hi, lo; split4(f, hi, lo);
        *(uint2*)&Ah[row * ASTR + ck4] = hi;
        *(uint2*)&Al[row * ASTR + ck4] = lo;
    }
    #pragma unroll
    for (int i = 0; i < 4; i++) {
        int e = tid + i * 256;
        int ck = e >> 4, nn4 = (e & 15) * 4;
        float4 f = *(const float4*)&g_yq[((size_t)(b * 64 + ck)) * N_ + n0 + nn4];
        uint2 hi, lo; split4(f, hi, lo);
        *(uint2*)&Bh[ck * BSTR + nn4] = hi;
        *(uint2*)&Bl[ck * BSTR + nn4] = lo;
    }
    __syncthreads();

    float acc[4][4] = {};
    #pragma unroll
    for (int ks = 0; ks < 4; ks++) {
        unsigned aStep = ks * 32;
        unsigned bStep = ks * 16 * (BSTR * 2);
        unsigned ah[4], al[4], bh[4], bl[4], bh2[4], bl2[4];
        LDSM_X4(ah, aOffH + aStep);
        LDSM_X4(al, aOffL + aStep);
        LDSM_X4T(bh, bOffH0 + bStep);
        LDSM_X4T(bl, bOffL0 + bStep);
        LDSM_X4T(bh2, bOffH1 + bStep);
        LDSM_X4T(bl2, bOffL1 + bStep);
        MMA_BF16(acc[0], ah, bh[0], bh[1]);
        MMA_BF16(acc[0], ah, bl[0], bl[1]);
        MMA_BF16(acc[0], al, bh[0], bh[1]);
        MMA_BF16(acc[1], ah, bh[2], bh[3]);
        MMA_BF16(acc[1], ah, bl[2], bl[3]);
        MMA_BF16(acc[1], al, bh[2], bh[3]);
        MMA_BF16(acc[2], ah, bh2[0], bh2[1]);
        MMA_BF16(acc[2], ah, bl2[0], bl2[1]);
        MMA_BF16(acc[2], al, bh2[0], bh2[1]);
        MMA_BF16(acc[3], ah, bh2[2], bh2[3]);
        MMA_BF16(acc[3], ah, bl2[2], bl2[3]);
        MMA_BF16(acc[3], al, bh2[2], bh2[3]);
    }

    int r4 = lane >> 2, c2 = (lane & 3) * 2;
    int row0 = co0 + ct + r4, row1 = row0 + 8;
    float b0v = g_obias[b * CO + row0], b1v = g_obias[b * CO + row1];
    #pragma unroll
    for (int t = 0; t < 4; t++) {
        int col = n0 + ng + t * 8 + c2;
        *(float2*)&out[((size_t)(b * CO + row0)) * N_ + col] =
            make_float2(acc[t][0] + b0v, acc[t][1] + b0v);
        *(float2*)&out[((size_t)(b * CO + row1)) * N_ + col] =
            make_float2(acc[t][2] + b1v, acc[t][3] + b1v);
    }
}

// ---------------- launch ----------------
extern "C" void kernel_launch(void* const* d_in, const int* in_sizes, int n_in,
                              void* d_out, int out_size) {
    const float* q     = (const float*)d_in[0];
    const float* k     = (const float*)d_in[1];
    const float* v     = (const float*)d_in[2];
    const float* Wk    = (const float*)d_in[3];
    const float* bk    = (const float*)d_in[4];
    const float* gamma = (const float*)d_in[5];
    const float* beta  = (const float*)d_in[6];
    const float* Wv    = (const float*)d_in[7];
    const float* bv    = (const float*)d_in[8];
    const float* Ww    = (const float*)d_in[9];
    const float* bw    = (const float*)d_in[10];
    float* out = (float*)d_out;

    conv_mma_kernel<<<dim3(64, B_, 3), 256>>>(q, k, v, Wk, Wv, bk, bv);
    bn_stats_kernel<<<128, 256>>>(gamma, beta);
    norm_kernel<<<256, 512>>>();
    kv_mma_kernel<<<dim3(KVCHUNKS, B_), 256>>>();
    m_kernel<<<B_, 256>>>(Ww, bw);
    out_mma_kernel<<<dim3(64, B_, 2), 256>>>(out);
}

// round 13
// speedup vs baseline: 1.7340x; 1.0192x over previous
#include <cuda_runtime.h>
#include <cuda_bf16.h>
#include <math.h>

#define B_   8
#define CIN  128
#define CK   64
#define CV   64
#define CO   128
#define N_   4096
#define KVCHUNKS 32

// ---------------- scratch ----------------
__device__ float g_yq[B_ * CK * N_];
__device__ float g_yk[B_ * CK * N_];
__device__ float g_yv[B_ * CV * N_];
__device__ float g_scale[2 * CK];
__device__ float g_shift[2 * CK];
__device__ float g_vsumpart[KVCHUNKS * B_ * CV];
__device__ float g_kvpart[KVCHUNKS * B_ * CK * CV];
__device__ float g_M[B_ * CO * CK];      // TRANSPOSED: [b][co][ck]
__device__ float g_obias[B_ * CO];

// ---------------- mma / ldmatrix helpers ----------------
__device__ __forceinline__ unsigned su32(const void* p) {
    return (unsigned)__cvta_generic_to_shared(p);
}
#define LDSM_X4(r, addr) \
    asm volatile("ldmatrix.sync.aligned.m8n8.x4.shared.b16 {%0,%1,%2,%3}, [%4];" \
        : "=r"((r)[0]), "=r"((r)[1]), "=r"((r)[2]), "=r"((r)[3]) : "r"(addr))
#define LDSM_X4T(r, addr) \
    asm volatile("ldmatrix.sync.aligned.m8n8.x4.trans.shared.b16 {%0,%1,%2,%3}, [%4];" \
        : "=r"((r)[0]), "=r"((r)[1]), "=r"((r)[2]), "=r"((r)[3]) : "r"(addr))
#define MMA_BF16(d, a, b0, b1) \
    asm volatile("mma.sync.aligned.m16n8k16.row.col.f32.bf16.bf16.f32 " \
        "{%0,%1,%2,%3}, {%4,%5,%6,%7}, {%8,%9}, {%0,%1,%2,%3};" \
        : "+f"((d)[0]), "+f"((d)[1]), "+f"((d)[2]), "+f"((d)[3]) \
        : "r"((a)[0]), "r"((a)[1]), "r"((a)[2]), "r"((a)[3]), "r"(b0), "r"(b1))

__device__ __forceinline__ unsigned packbf(__nv_bfloat16 lo, __nv_bfloat16 hi) {
    return ((unsigned)__bfloat16_as_ushort(hi) << 16) | __bfloat16_as_ushort(lo);
}
__device__ __forceinline__ void split4(float4 f, uint2 &hi, uint2 &lo) {
    __nv_bfloat16 hx = __float2bfloat16(f.x), hy = __float2bfloat16(f.y);
    __nv_bfloat16 hz = __float2bfloat16(f.z), hw = __float2bfloat16(f.w);
    __nv_bfloat16 lx = __float2bfloat16(f.x - __bfloat162float(hx));
    __nv_bfloat16 ly = __float2bfloat16(f.y - __bfloat162float(hy));
    __nv_bfloat16 lz = __float2bfloat16(f.z - __bfloat162float(hz));
    __nv_bfloat16 lw = __float2bfloat16(f.w - __bfloat162float(hw));
    hi.x = packbf(hx, hy); hi.y = packbf(hz, hw);
    lo.x = packbf(lx, ly); lo.y = packbf(lz, lw);
}

#define ASTR 72
#define BSTR 72

// ---------------- K1: 1x1 conv via bf16-split MMA (x-tile reg prefetch) ------
__global__ __launch_bounds__(256) void conv_mma_kernel(
    const float* __restrict__ xq, const float* __restrict__ xk,
    const float* __restrict__ xv,
    const float* __restrict__ Wk, const float* __restrict__ Wv,
    const float* __restrict__ bk, const float* __restrict__ bv)
{
    int which = blockIdx.z;
    const float* x    = (which == 0) ? xq : (which == 1) ? xk : xv;
    const float* W    = (which == 2) ? Wv : Wk;
    const float* bias = (which == 2) ? bv : bk;
    float* y          = (which == 0) ? g_yq : (which == 1) ? g_yk : g_yv;

    int bb = blockIdx.y;
    int n0 = blockIdx.x * 64;
    int tid = threadIdx.x;
    int lane = tid & 31, w = tid >> 5;
    int ct = (w & 3) * 16;
    int ng = (w >> 2) * 32;

    __shared__ __align__(16) __nv_bfloat16 Ah[64 * ASTR];
    __shared__ __align__(16) __nv_bfloat16 Al[64 * ASTR];
    __shared__ __align__(16) __nv_bfloat16 Bh[64 * BSTR];
    __shared__ __align__(16) __nv_bfloat16 Bl[64 * BSTR];

    int q = lane >> 3, rr = lane & 7;
    unsigned aOffH, aOffL, bOffH0, bOffL0, bOffH1, bOffL1;
    {
        int arow = ct + (q & 1) * 8 + rr;
        int acol = (q >> 1) * 8;
        aOffH = su32(Ah) + arow * (ASTR * 2) + acol * 2;
        aOffL = su32(Al) + arow * (ASTR * 2) + acol * 2;
        int brow = (q & 1) * 8 + rr;
        int bcol0 = ng + (q >> 1) * 8;
        int bcol1 = ng + 16 + (q >> 1) * 8;
        bOffH0 = su32(Bh) + brow * (BSTR * 2) + bcol0 * 2;
        bOffL0 = su32(Bl) + brow * (BSTR * 2) + bcol0 * 2;
        bOffH1 = su32(Bh) + brow * (BSTR * 2) + bcol1 * 2;
        bOffL1 = su32(Bl) + brow * (BSTR * 2) + bcol1 * 2;
    }

    // per-thread x-tile load coords (fixed across stages)
    int xci = tid >> 4, xnn4 = (tid & 15) * 4;
    const float* xbase = &x[((size_t)(bb * CIN + xci)) * N_ + n0 + xnn4];

    float acc[4][4] = {};
    float4 xreg[4];
    // preload stage 0 x-tile
    #pragma unroll
    for (int i = 0; i < 4; i++)
        xreg[i] = *(const float4*)(xbase + (size_t)(i * 16) * N_);

    for (int s = 0; s < 2; s++) {
        #pragma unroll
        for (int i = 0; i < 4; i++) {
            int e = tid + i * 256;
            int co = e >> 4, ci4 = (e & 15) * 4;
            float4 f = *(const float4*)&W[co * CIN + s * 64 + ci4];
            uint2 hi, lo; split4(f, hi, lo);
            *(uint2*)&Ah[co * ASTR + ci4] = hi;
            *(uint2*)&Al[co * ASTR + ci4] = lo;
        }
        #pragma unroll
        for (int i = 0; i < 4; i++) {
            int ci = xci + i * 16;
            uint2 hi, lo; split4(xreg[i], hi, lo);
            *(uint2*)&Bh[ci * BSTR + xnn4] = hi;
            *(uint2*)&Bl[ci * BSTR + xnn4] = lo;
        }
        __syncthreads();

        if (s == 0) {
            // prefetch stage 1 x-tile; latency hides under the MMA loop
            #pragma unroll
            for (int i = 0; i < 4; i++)
                xreg[i] = *(const float4*)(xbase + (size_t)(64 + i * 16) * N_);
        }

        #pragma unroll
        for (int ks = 0; ks < 4; ks++) {
            unsigned aStep = ks * 32;
            unsigned bStep = ks * 16 * (BSTR * 2);
            unsigned ah[4], al[4], bh[4], bl[4], bh2[4], bl2[4];
            LDSM_X4(ah, aOffH + aStep);
            LDSM_X4(al, aOffL + aStep);
            LDSM_X4T(bh, bOffH0 + bStep);
            LDSM_X4T(bl, bOffL0 + bStep);
            LDSM_X4T(bh2, bOffH1 + bStep);
            LDSM_X4T(bl2, bOffL1 + bStep);
            MMA_BF16(acc[0], ah, bh[0], bh[1]);
            MMA_BF16(acc[0], ah, bl[0], bl[1]);
            MMA_BF16(acc[0], al, bh[0], bh[1]);
            MMA_BF16(acc[1], ah, bh[2], bh[3]);
            MMA_BF16(acc[1], ah, bl[2], bl[3]);
            MMA_BF16(acc[1], al, bh[2], bh[3]);
            MMA_BF16(acc[2], ah, bh2[0], bh2[1]);
            MMA_BF16(acc[2], ah, bl2[0], bl2[1]);
            MMA_BF16(acc[2], al, bh2[0], bh2[1]);
            MMA_BF16(acc[3], ah, bh2[2], bh2[3]);
            MMA_BF16(acc[3], ah, bl2[2], bl2[3]);
            MMA_BF16(acc[3], al, bh2[2], bh2[3]);
        }
        __syncthreads();
    }

    int r4 = lane >> 2, c2 = (lane & 3) * 2;
    int row0 = ct + r4, row1 = ct + r4 + 8;
    float b0v = bias[row0], b1v = bias[row1];
    #pragma unroll
    for (int t = 0; t < 4; t++) {
        int col = n0 + ng + t * 8 + c2;
        *(float2*)&y[((size_t)(bb * 64 + row0)) * N_ + col] =
            make_float2(acc[t][0] + b0v, acc[t][1] + b0v);
        *(float2*)&y[((size_t)(bb * 64 + row1)) * N_ + col] =
            make_float2(acc[t][2] + b1v, acc[t][3] + b1v);
    }
}

// ---------------- K2: BN batch stats ----------------
__global__ __launch_bounds__(256) void bn_stats_kernel(
    const float* __restrict__ gamma, const float* __restrict__ beta)
{
    int c = blockIdx.x & 63;
    int which = blockIdx.x >> 6;
    const float* y = which ? g_yk : g_yq;
    int tid = threadIdx.x;

    float s = 0.f, ss = 0.f;
    #pragma unroll
    for (int b = 0; b < B_; b++) {
        const float4* row = (const float4*)(y + ((size_t)(b * 64 + c)) * N_);
        #pragma unroll
        for (int i = 0; i < 4; i++) {
            float4 f = row[tid + i * 256];
            s  += f.x + f.y + f.z + f.w;
            ss += f.x * f.x + f.y * f.y + f.z * f.z + f.w * f.w;
        }
    }
    #pragma unroll
    for (int o = 16; o; o >>= 1) {
        s  += __shfl_down_sync(0xffffffffu, s, o);
        ss += __shfl_down_sync(0xffffffffu, ss, o);
    }
    __shared__ float rs[8], rss[8];
    int wid = tid >> 5, lane = tid & 31;
    if (lane == 0) { rs[wid] = s; rss[wid] = ss; }
    __syncthreads();
    if (tid == 0) {
        float S = 0.f, SS = 0.f;
        #pragma unroll
        for (int i = 0; i < 8; i++) { S += rs[i]; SS += rss[i]; }
        const float inv = 1.0f / 32768.0f;
        float mean = S * inv;
        float var  = SS * inv - mean * mean;
        float sc = gamma[c] * rsqrtf(var + 1e-5f);
        g_scale[blockIdx.x] = sc;
        g_shift[blockIdx.x] = beta[c] - mean * sc;
    }
}

// ---------------- K3: apply BN + L2-normalize (float2, 16ch x 2col/thread) ---
__global__ __launch_bounds__(512) void norm_kernel() {
    int blk = blockIdx.x;
    int which = blk >> 7;
    int r = blk & 127;
    int b = r >> 4;
    int n0 = (r & 15) * 256;
    float* y = which ? g_yk : g_yq;
    int tid = threadIdx.x;
    int qt = tid >> 7;
    int l = tid & 127;
    int n = n0 + l * 2;

    __shared__ float scs[64], shs[64];
    __shared__ float ss4[4][256];
    if (tid < 64) {
        scs[tid] = g_scale[which * 64 + tid];
        shs[tid] = g_shift[which * 64 + tid];
    }
    __syncthreads();

    float2 v[16];
    float ssa = 0.f, ssb = 0.f;
    #pragma unroll
    for (int i = 0; i < 16; i++) {
        int c = qt * 16 + i;
        float2 t = *(const float2*)&y[((size_t)(b * 64 + c)) * N_ + n];
        t.x = t.x * scs[c] + shs[c];
        t.y = t.y * scs[c] + shs[c];
        v[i] = t;
        ssa += t.x * t.x;  ssb += t.y * t.y;
    }
    ss4[qt][l * 2] = ssa;  ss4[qt][l * 2 + 1] = ssb;
    __syncthreads();
    float rna = 1.0f / (sqrtf(ss4[0][l*2]   + ss4[1][l*2]   + ss4[2][l*2]   + ss4[3][l*2])   + 1e-7f);
    float rnb = 1.0f / (sqrtf(ss4[0][l*2+1] + ss4[1][l*2+1] + ss4[2][l*2+1] + ss4[3][l*2+1]) + 1e-7f);
    #pragma unroll
    for (int i = 0; i < 16; i++) {
        int c = qt * 16 + i;
        *(float2*)&y[((size_t)(b * 64 + c)) * N_ + n] = make_float2(v[i].x * rna, v[i].y * rnb);
    }
}

// ---------------- K4: KV via bf16-split MMA (K/V reg prefetch) ---------------
__global__ __launch_bounds__(256) void kv_mma_kernel() {
    int chunk = blockIdx.x, b = blockIdx.y;
    int tid = threadIdx.x;
    int lane = tid & 31, w = tid >> 5;
    int ct = (w & 3) * 16;
    int cg = (w >> 2) * 32;

    __shared__ __align__(16) __nv_bfloat16 Kh[64 * ASTR];
    __shared__ __align__(16) __nv_bfloat16 Kl[64 * ASTR];
    __shared__ __align__(16) __nv_bfloat16 Vh[64 * ASTR];
    __shared__ __align__(16) __nv_bfloat16 Vl[64 * ASTR];
    __shared__ float vps[64][4];

    int q = lane >> 3, rr = lane & 7;
    unsigned aH, aL, bH0, bL0, bH1, bL1;
    {
        int arow = ct + (q & 1) * 8 + rr;
        int acol = (q >> 1) * 8;
        aH = su32(Kh) + arow * (ASTR * 2) + acol * 2;
        aL = su32(Kl) + arow * (ASTR * 2) + acol * 2;
        int brow = cg + (q >> 1) * 8 + rr;
        int bcol = (q & 1) * 8;
        bH0 = su32(Vh) + brow * (ASTR * 2) + bcol * 2;
        bL0 = su32(Vl) + brow * (ASTR * 2) + bcol * 2;
        bH1 = bH0 + 16 * (ASTR * 2);
        bL1 = bL0 + 16 * (ASTR * 2);
    }

    int cc = tid & 63, q4 = tid >> 6;
    int lrow = tid >> 4, lnn4 = (tid & 15) * 4;   // per-thread load coords
    const float* kbase = &g_yk[((size_t)(b * 64 + lrow)) * N_ + chunk * 128 + lnn4];
    const float* vbase = &g_yv[((size_t)(b * 64 + lrow)) * N_ + chunk * 128 + lnn4];

    float acc[4][4] = {};
    float vp = 0.f;
    float4 kreg[4], vreg[4];
    // preload tile 0
    #pragma unroll
    for (int i = 0; i < 4; i++) {
        kreg[i] = *(const float4*)(kbase + (size_t)(i * 16) * N_);
        vreg[i] = *(const float4*)(vbase + (size_t)(i * 16) * N_);
    }

    for (int t = 0; t < 2; t++) {
        #pragma unroll
        for (int i = 0; i < 4; i++) {
            int row = lrow + i * 16;
            uint2 hi, lo;
            split4(kreg[i], hi, lo);
            *(uint2*)&Kh[row * ASTR + lnn4] = hi;
            *(uint2*)&Kl[row * ASTR + lnn4] = lo;
            split4(vreg[i], hi, lo);
            *(uint2*)&Vh[row * ASTR + lnn4] = hi;
            *(uint2*)&Vl[row * ASTR + lnn4] = lo;
        }
        __syncthreads();

        if (t == 0) {
            // prefetch tile 1; latency hides under the MMA loop
            #pragma unroll
            for (int i = 0; i < 4; i++) {
                kreg[i] = *(const float4*)(kbase + (size_t)(i * 16) * N_ + 64);
                vreg[i] = *(const float4*)(vbase + (size_t)(i * 16) * N_ + 64);
            }
        }

        #pragma unroll
        for (int ks = 0; ks < 4; ks++) {
            unsigned step = ks * 32;
            unsigned ah[4], al[4], bh[4], bl[4], bh2[4], bl2[4];
            LDSM_X4(ah, aH + step);
            LDSM_X4(al, aL + step);
            LDSM_X4(bh, bH0 + step);
            LDSM_X4(bl, bL0 + step);
            LDSM_X4(bh2, bH1 + step);
            LDSM_X4(bl2, bL1 + step);
            MMA_BF16(acc[0], ah, bh[0], bh[1]);
            MMA_BF16(acc[0], ah, bl[0], bl[1]);
            MMA_BF16(acc[0], al, bh[0], bh[1]);
            MMA_BF16(acc[1], ah, bh[2], bh[3]);
            MMA_BF16(acc[1], ah, bl[2], bl[3]);
            MMA_BF16(acc[1], al, bh[2], bh[3]);
            MMA_BF16(acc[2], ah, bh2[0], bh2[1]);
            MMA_BF16(acc[2], ah, bl2[0], bl2[1]);
            MMA_BF16(acc[2], al, bh2[0], bh2[1]);
            MMA_BF16(acc[3], ah, bh2[2], bh2[3]);
            MMA_BF16(acc[3], ah, bl2[2], bl2[3]);
            MMA_BF16(acc[3], al, bh2[2], bh2[3]);
        }
        // fused V row sums (hi+lo) from smem bf16
        #pragma unroll
        for (int i = 0; i < 16; i++) {
            int idx = cc * ASTR + q4 * 16 + i;
            vp += __bfloat162float(Vh[idx]) + __bfloat162float(Vl[idx]);
        }
        __syncthreads();
    }

    int r4 = lane >> 2, c2 = (lane & 3) * 2;
    int row0 = ct + r4, row1 = ct + r4 + 8;
    float* base = &g_kvpart[(((size_t)chunk * B_ + b)) * 4096];
    #pragma unroll
    for (int t = 0; t < 4; t++) {
        int col = cg + t * 8 + c2;
        *(float2*)&base[row0 * 64 + col] = make_float2(acc[t][0], acc[t][1]);
        *(float2*)&base[row1 * 64 + col] = make_float2(acc[t][2], acc[t][3]);
    }

    vps[cc][q4] = vp;
    __syncthreads();
    if (tid < 64)
        g_vsumpart[((size_t)chunk * B_ + b) * 64 + tid] =
            vps[tid][0] + vps[tid][1] + vps[tid][2] + vps[tid][3];
}

// ---------------- K5: M^T = (KV @ Ww^T)^T; obias ----------------------------
__global__ __launch_bounds__(256) void m_kernel(
    const float* __restrict__ Ww, const float* __restrict__ bw)
{
    int b = blockIdx.x;
    __shared__ float KVs[64][64];
    __shared__ float WwT[64][128];
    __shared__ float vs_s[64];
    int tid = threadIdx.x;

    if (tid < 64) {
        float S = 0.f;
        #pragma unroll
        for (int c2 = 0; c2 < KVCHUNKS; c2++)
            S += g_vsumpart[((size_t)c2 * B_ + b) * 64 + tid];
        vs_s[tid] = S;
    }
    for (int e = tid; e < 4096; e += 256) {
        float s = 0.f;
        #pragma unroll
        for (int c2 = 0; c2 < KVCHUNKS; c2++)
            s += g_kvpart[((size_t)c2 * B_ + b) * 4096 + e];
        KVs[e >> 6][e & 63] = s;
    }
    for (int e = tid; e < 8192; e += 256) {
        int cv = e >> 7, co = e & 127;
        WwT[cv][co] = Ww[co * CV + cv];
    }
    __syncthreads();

    int co = tid & 127;
    for (int ck = (tid >> 7); ck < 64; ck += 2) {
        float s = 0.f;
        #pragma unroll 8
        for (int cv = 0; cv < 64; cv++) s += KVs[ck][cv] * WwT[cv][co];
        g_M[((size_t)b * 128 + co) * 64 + ck] = s;
    }
    if (tid < 128) {
        float s = bw[tid];
        #pragma unroll 8
        for (int cv = 0; cv < 64; cv++) s += vs_s[cv] * WwT[cv][tid];
        g_obias[b * CO + tid] = s;
    }
}

// ---------------- K6: out via bf16-split MMA ---------------------------------
__global__ __launch_bounds__(256) void out_mma_kernel(float* __restrict__ out) {
    int b = blockIdx.y, n0 = blockIdx.x * 64, ch = blockIdx.z;
    int co0 = ch * 64;
    int tid = threadIdx.x;
    int lane = tid & 31, w = tid >> 5;
    int ct = (w & 3) * 16;
    int ng = (w >> 2) * 32;

    __shared__ __align__(16) __nv_bfloat16 Ah[64 * ASTR];
    __shared__ __align__(16) __nv_bfloat16 Al[64 * ASTR];
    __shared__ __align__(16) __nv_bfloat16 Bh[64 * BSTR];
    __shared__ __align__(16) __nv_bfloat16 Bl[64 * BSTR];

    int q = lane >> 3, rr = lane & 7;
    unsigned aOffH, aOffL, bOffH0, bOffL0, bOffH1, bOffL1;
    {
        int arow = ct + (q & 1) * 8 + rr;
        int acol = (q >> 1) * 8;
        aOffH = su32(Ah) + arow * (ASTR * 2) + acol * 2;
        aOffL = su32(Al) + arow * (ASTR * 2) + acol * 2;
        int brow = (q & 1) * 8 + rr;
        int bcol0 = ng + (q >> 1) * 8;
        int bcol1 = ng + 16 + (q >> 1) * 8;
        bOffH0 = su32(Bh) + brow * (BSTR * 2) + bcol0 * 2;
        bOffL0 = su32(Bl) + brow * (BSTR * 2) + bcol0 * 2;
        bOffH1 = su32(Bh) + brow * (BSTR * 2) + bcol1 * 2;
        bOffL1 = su32(Bl) + brow * (BSTR * 2) + bcol1 * 2;
    }

    #pragma unroll
    for (int i = 0; i < 4; i++) {
        int e = tid + i * 256;
        int row = e >> 4, ck4 = (e & 15) * 4;
        float4 f = *(const float4*)&g_M[((size_t)b * 128 + co0 + row) * 64 + ck4];
        uint2 hi, lo; split4(f, hi, lo);
        *(uint2*)&Ah[row * ASTR + ck4] = hi;
        *(uint2*)&Al[row * ASTR + ck4] = lo;
    }
    #pragma unroll
    for (int i = 0; i < 4; i++) {
        int e = tid + i * 256;
        int ck = e >> 4, nn4 = (e & 15) * 4;
        float4 f = *(const float4*)&g_yq[((size_t)(b * 64 + ck)) * N_ + n0 + nn4];
        uint2 hi, lo; split4(f, hi, lo);
        *(uint2*)&Bh[ck * BSTR + nn4] = hi;
        *(uint2*)&Bl[ck * BSTR + nn4] = lo;
    }
    __syncthreads();

    float acc[4][4] = {};
    #pragma unroll
    for (int ks = 0; ks < 4; ks++) {
        unsigned aStep = ks * 32;
        unsigned bStep = ks * 16 * (BSTR * 2);
        unsigned ah[4], al[4], bh[4], bl[4], bh2[4], bl2[4];
        LDSM_X4(ah, aOffH + aStep);
        LDSM_X4(al, aOffL + aStep);
        LDSM_X4T(bh, bOffH0 + bStep);
        LDSM_X4T(bl, bOffL0 + bStep);
        LDSM_X4T(bh2, bOffH1 + bStep);
        LDSM_X4T(bl2, bOffL1 + bStep);
        MMA_BF16(acc[0], ah, bh[0], bh[1]);
        MMA_BF16(acc[0], ah, bl[0], bl[1]);
        MMA_BF16(acc[0], al, bh[0], bh[1]);
        MMA_BF16(acc[1], ah, bh[2], bh[3]);
        MMA_BF16(acc[1], ah, bl[2], bl[3]);
        MMA_BF16(acc[1], al, bh[2], bh[3]);
        MMA_BF16(acc[2], ah, bh2[0], bh2[1]);
        MMA_BF16(acc[2], ah, bl2[0], bl2[1]);
        MMA_BF16(acc[2], al, bh2[0], bh2[1]);
        MMA_BF16(acc[3], ah, bh2[2], bh2[3]);
        MMA_BF16(acc[3], ah, bl2[2], bl2[3]);
        MMA_BF16(acc[3], al, bh2[2], bh2[3]);
    }

    int r4 = lane >> 2, c2 = (lane & 3) * 2;
    int row0 = co0 + ct + r4, row1 = row0 + 8;
    float b0v = g_obias[b * CO + row0], b1v = g_obias[b * CO + row1];
    #pragma unroll
    for (int t = 0; t < 4; t++) {
        int col = n0 + ng + t * 8 + c2;
        *(float2*)&out[((size_t)(b * CO + row0)) * N_ + col] =
            make_float2(acc[t][0] + b0v, acc[t][1] + b0v);
        *(float2*)&out[((size_t)(b * CO + row1)) * N_ + col] =
            make_float2(acc[t][2] + b1v, acc[t][3] + b1v);
    }
}

// ---------------- launch ----------------
extern "C" void kernel_launch(void* const* d_in, const int* in_sizes, int n_in,
                              void* d_out, int out_size) {
    const float* q     = (const float*)d_in[0];
    const float* k     = (const float*)d_in[1];
    const float* v     = (const float*)d_in[2];
    const float* Wk    = (const float*)d_in[3];
    const float* bk    = (const float*)d_in[4];
    const float* gamma = (const float*)d_in[5];
    const float* beta  = (const float*)d_in[6];
    const float* Wv    = (const float*)d_in[7];
    const float* bv    = (const float*)d_in[8];
    const float* Ww    = (const float*)d_in[9];
    const float* bw    = (const float*)d_in[10];
    float* out = (float*)d_out;

    conv_mma_kernel<<<dim3(64, B_, 3), 256>>>(q, k, v, Wk, Wv, bk, bv);
    bn_stats_kernel<<<128, 256>>>(gamma, beta);
    norm_kernel<<<256, 512>>>();
    kv_mma_kernel<<<dim3(KVCHUNKS, B_), 256>>>();
    m_kernel<<<B_, 256>>>(Ww, bw);
    out_mma_kernel<<<dim3(64, B_, 2), 256>>>(out);
}